// round 7
// baseline (speedup 1.0000x reference)
#include <cuda_runtime.h>

#define BB    8
#define DD    472
#define CC    472
#define FHH   56
#define FWW   100
#define NPIX  (FHH * FWW)      // 5600
#define NXX   160
#define NYY   160

#define SEGS       8
#define BINS_SEG   59                      // 8 * 59 = 472
#define ARG_BLOCKS ((BB * NPIX) / 32)      // 1400
#define ZERO_BLOCKS 8192
#define NGROUP     (BB * NPIX / 8)         // 5600 groups of 8 pixels

// per-pixel BEV segment (or -1), rewritten fully every launch
__device__ int pix2seg_g[BB * NPIX];

__device__ __forceinline__ void inv3x3(const float a[9], float m[9]) {
    float A  =  (a[4] * a[8] - a[5] * a[7]);
    float Bc = -(a[3] * a[8] - a[5] * a[6]);
    float Cc =  (a[3] * a[7] - a[4] * a[6]);
    float Dv = -(a[1] * a[8] - a[2] * a[7]);
    float E  =  (a[0] * a[8] - a[2] * a[6]);
    float F  = -(a[0] * a[7] - a[1] * a[6]);
    float G  =  (a[1] * a[5] - a[2] * a[4]);
    float Hc = -(a[0] * a[5] - a[2] * a[3]);
    float I  =  (a[0] * a[4] - a[1] * a[3]);
    float det = a[0] * A + a[1] * Bc + a[2] * Cc;
    m[0] = A  / det;  m[1] = Dv / det;  m[2] = G  / det;
    m[3] = Bc / det;  m[4] = E  / det;  m[5] = Hc / det;
    m[6] = Cc / det;  m[7] = F  / det;  m[8] = I  / det;
}

// Fused: blocks [0, ARG_BLOCKS) -> depth argmax + geometry -> pix2seg_g.
//        blocks [ARG_BLOCKS, ...) -> zero-fill output. Disjoint memory.
__global__ void __launch_bounds__(256)
fused_kernel(const float* __restrict__ depth,   // [B, D, FH, FW]
             const float* __restrict__ intr,    // [B, 3, 3]
             const float* __restrict__ rot,     // [B, 3, 3]
             float* __restrict__ out,           // [B, NX, NY, C]
             long long nout)
{
    if (blockIdx.x >= ARG_BLOCKS) {
        long long n4 = nout >> 2;
        float4* o4 = reinterpret_cast<float4*>(out);
        long long i = (long long)(blockIdx.x - ARG_BLOCKS) * 256 + threadIdx.x;
        long long stride = (long long)(gridDim.x - ARG_BLOCKS) * 256;
        float4 z = make_float4(0.f, 0.f, 0.f, 0.f);
        for (; i < n4; i += stride) o4[i] = z;
        return;
    }

    // ---- argmax: 32 pixels per block, 8 depth-segments (one warp each) ----
    int tx = threadIdx.x & 31;    // pixel within tile
    int ty = threadIdx.x >> 5;    // depth segment
    int pix = blockIdx.x * 32 + tx;
    int b  = pix / NPIX;
    int hw = pix - b * NPIX;

    const float* dp = depth + (size_t)b * DD * NPIX + hw;
    int base = ty * BINS_SEG;
    float best = dp[(size_t)base * NPIX];
    int   bi   = base;
    #pragma unroll
    for (int k = 1; k < BINS_SEG; k++) {
        float v = dp[(size_t)(base + k) * NPIX];
        if (v > best) { best = v; bi = base + k; }
    }

    __shared__ float sval[SEGS][32];
    __shared__ int   sidx[SEGS][32];
    sval[ty][tx] = best;
    sidx[ty][tx] = bi;
    __syncthreads();
    if (ty != 0) return;

    // reduce across depth segments in ascending order (first max wins)
    float bv = sval[0][tx];
    int  bix = sidx[0][tx];
    #pragma unroll
    for (int s = 1; s < SEGS; s++) {
        float v = sval[s][tx];
        if (v > bv) { bv = v; bix = sidx[s][tx]; }
    }
    float d = (float)bix * 0.125f + 1.0f;

    // combine = R * inv(K), float32, ascending-j fma
    float a[9], invK[9], Cm[9];
    #pragma unroll
    for (int i = 0; i < 9; i++) a[i] = intr[b * 9 + i];
    inv3x3(a, invK);
    #pragma unroll
    for (int i = 0; i < 3; i++) {
        #pragma unroll
        for (int j = 0; j < 3; j++) {
            float acc = rot[b * 9 + i * 3 + 0] * invK[0 * 3 + j];
            acc = fmaf(rot[b * 9 + i * 3 + 1], invK[1 * 3 + j], acc);
            acc = fmaf(rot[b * 9 + i * 3 + 2], invK[2 * 3 + j], acc);
            Cm[i * 3 + j] = acc;
        }
    }

    int h = hw / FWW;
    int w = hw - h * FWW;
    const float DU = 1600.0f / 99.0f;
    const float DV = 896.0f / 55.0f;
    float u  = (float)w * DU;
    float v  = (float)h * DV;
    float ud = u * d;
    float vd = v * d;

    float x = fmaf(Cm[2], d, fmaf(Cm[1], vd, Cm[0] * ud));
    float y = fmaf(Cm[5], d, fmaf(Cm[4], vd, Cm[3] * ud));
    float z = fmaf(Cm[8], d, fmaf(Cm[7], vd, Cm[6] * ud));

    bool inb = (x > 1.0f) && (x < 41.0f) &&
               (y > -20.0f) && (y < 20.0f) &&
               (z > -10.0f) && (z < 10.0f);
    float fxv = floorf((x - 1.0f) * 4.0f);
    float fyv = floorf((y + 20.0f) * 4.0f);
    float fzv = floorf((z + 10.0f) / 20.0f);
    int xi = (int)fxv, yi = (int)fyv, zi = (int)fzv;
    bool ing = (xi >= 0) && (xi < NXX) && (yi >= 0) && (yi < NYY) &&
               (zi >= 0) && (zi < 1);

    pix2seg_g[pix] = (inb && ing) ? ((b * NXX + xi) * NYY + yi) : -1;
}

// Scatter: one warp per 8 consecutive pixels. Lane = (c_sub, p) with
// c_sub = lane>>3 (4 channels), p = lane&7 (8 pixels). Reads are fully
// coalesced (8 consecutive floats per c_sub -> whole 32B sectors).
__global__ void __launch_bounds__(256)
scatter_kernel(const float* __restrict__ feats,   // [B, C, FH, FW]
               float* __restrict__ out)           // [B*NX*NY, C]
{
    int grp  = (blockIdx.x * 256 + threadIdx.x) >> 5;
    int lane = threadIdx.x & 31;
    if (grp >= NGROUP) return;

    int p    = lane & 7;     // pixel within group
    int csub = lane >> 3;    // channel sub-index (0..3)

    int gpix0 = grp * 8;               // NPIX % 8 == 0: groups never straddle b
    int b   = gpix0 / NPIX;
    int hw0 = gpix0 - b * NPIX;

    int seg = pix2seg_g[gpix0 + p];    // this lane's pixel's segment (dup x4)
    if (__ballot_sync(0xffffffffu, seg >= 0) == 0) return;

    bool valid = (seg >= 0);
    const float* fp = feats + (size_t)b * CC * NPIX + hw0 + p;
    float* op = out + (size_t)(valid ? seg : 0) * CC;

    #pragma unroll 2
    for (int chunk = 0; chunk < CC / 4; chunk++) {
        int c = chunk * 4 + csub;
        float v = __ldg(&fp[(size_t)c * NPIX]);
        if (valid) atomicAdd(&op[c], v);
    }
}

extern "C" void kernel_launch(void* const* d_in, const int* in_sizes, int n_in,
                              void* d_out, int out_size) {
    const float* depth = (const float*)d_in[0];
    const float* feats = (const float*)d_in[1];
    const float* intr  = (const float*)d_in[2];
    const float* rot   = (const float*)d_in[3];
    float* out = (float*)d_out;

    fused_kernel<<<ARG_BLOCKS + ZERO_BLOCKS, 256>>>(depth, intr, rot, out,
                                                    (long long)out_size);

    int blocks = (NGROUP * 32 + 255) / 256;   // 700
    scatter_kernel<<<blocks, 256>>>(feats, out);
}

// round 8
// speedup vs baseline: 1.6860x; 1.6860x over previous
#include <cuda_runtime.h>

#define BB    8
#define DD    472
#define CC    472
#define FHH   56
#define FWW   100
#define NPIX  (FHH * FWW)      // 5600
#define NXX   160
#define NYY   160

#define SEGS       8
#define BINS_SEG   59                      // 8 * 59 = 472
#define ARG_BLOCKS ((BB * NPIX) / 32)      // 1400
#define ZERO_BLOCKS 8072                   // 1400+8072 = 9472 = 8 * 1184 (full waves)
#define NCHUNK     (CC / 4)                // 118 float4 chunks per segment

// per-pixel BEV segment (or -1), rewritten fully every launch
__device__ int pix2seg_g[BB * NPIX];

__device__ __forceinline__ void inv3x3(const float a[9], float m[9]) {
    float A  =  (a[4] * a[8] - a[5] * a[7]);
    float Bc = -(a[3] * a[8] - a[5] * a[6]);
    float Cc =  (a[3] * a[7] - a[4] * a[6]);
    float Dv = -(a[1] * a[8] - a[2] * a[7]);
    float E  =  (a[0] * a[8] - a[2] * a[6]);
    float F  = -(a[0] * a[7] - a[1] * a[6]);
    float G  =  (a[1] * a[5] - a[2] * a[4]);
    float Hc = -(a[0] * a[5] - a[2] * a[3]);
    float I  =  (a[0] * a[4] - a[1] * a[3]);
    float det = a[0] * A + a[1] * Bc + a[2] * Cc;
    m[0] = A  / det;  m[1] = Dv / det;  m[2] = G  / det;
    m[3] = Bc / det;  m[4] = E  / det;  m[5] = Hc / det;
    m[6] = Cc / det;  m[7] = F  / det;  m[8] = I  / det;
}

__device__ __forceinline__ void red_add_v4(float* addr, float a, float b,
                                           float c, float d) {
    asm volatile("red.global.add.v4.f32 [%0], {%1, %2, %3, %4};"
                 :: "l"(addr), "f"(a), "f"(b), "f"(c), "f"(d) : "memory");
}

// Fused: blocks [0, ARG_BLOCKS) -> depth argmax + geometry -> pix2seg_g,
//        (PDL trigger after pix2seg write). Blocks [ARG_BLOCKS,...) -> zero.
__global__ void __launch_bounds__(256)
fused_kernel(const float* __restrict__ depth,   // [B, D, FH, FW]
             const float* __restrict__ intr,    // [B, 3, 3]
             const float* __restrict__ rot,     // [B, 3, 3]
             float* __restrict__ out,           // [B, NX, NY, C]
             long long nout)
{
    if (blockIdx.x >= ARG_BLOCKS) {
        cudaTriggerProgrammaticLaunchCompletion();
        long long n4 = nout >> 2;
        float4* o4 = reinterpret_cast<float4*>(out);
        long long i = (long long)(blockIdx.x - ARG_BLOCKS) * 256 + threadIdx.x;
        long long stride = (long long)(gridDim.x - ARG_BLOCKS) * 256;
        float4 z = make_float4(0.f, 0.f, 0.f, 0.f);
        for (; i < n4; i += stride) __stcs(&o4[i], z);
        return;
    }

    // ---- argmax: 32 pixels per block, 8 depth-segments (one warp each) ----
    int tx = threadIdx.x & 31;    // pixel within tile
    int ty = threadIdx.x >> 5;    // depth segment
    int pix = blockIdx.x * 32 + tx;
    int b  = pix / NPIX;
    int hw = pix - b * NPIX;

    const float* dp = depth + (size_t)b * DD * NPIX + hw;
    int base = ty * BINS_SEG;
    float best = dp[(size_t)base * NPIX];
    int   bi   = base;
    #pragma unroll
    for (int k = 1; k < BINS_SEG; k++) {
        float v = dp[(size_t)(base + k) * NPIX];
        if (v > best) { best = v; bi = base + k; }
    }

    __shared__ float sval[SEGS][32];
    __shared__ int   sidx[SEGS][32];
    sval[ty][tx] = best;
    sidx[ty][tx] = bi;
    __syncthreads();

    if (ty == 0) {
        // reduce across depth segments in ascending order (first max wins)
        float bv = sval[0][tx];
        int  bix = sidx[0][tx];
        #pragma unroll
        for (int s = 1; s < SEGS; s++) {
            float v = sval[s][tx];
            if (v > bv) { bv = v; bix = sidx[s][tx]; }
        }
        float d = (float)bix * 0.125f + 1.0f;

        // combine = R * inv(K), float32, ascending-j fma
        float a[9], invK[9], Cm[9];
        #pragma unroll
        for (int i = 0; i < 9; i++) a[i] = intr[b * 9 + i];
        inv3x3(a, invK);
        #pragma unroll
        for (int i = 0; i < 3; i++) {
            #pragma unroll
            for (int j = 0; j < 3; j++) {
                float acc = rot[b * 9 + i * 3 + 0] * invK[0 * 3 + j];
                acc = fmaf(rot[b * 9 + i * 3 + 1], invK[1 * 3 + j], acc);
                acc = fmaf(rot[b * 9 + i * 3 + 2], invK[2 * 3 + j], acc);
                Cm[i * 3 + j] = acc;
            }
        }

        int h = hw / FWW;
        int w = hw - h * FWW;
        const float DU = 1600.0f / 99.0f;
        const float DV = 896.0f / 55.0f;
        float u  = (float)w * DU;
        float v  = (float)h * DV;
        float ud = u * d;
        float vd = v * d;

        float x = fmaf(Cm[2], d, fmaf(Cm[1], vd, Cm[0] * ud));
        float y = fmaf(Cm[5], d, fmaf(Cm[4], vd, Cm[3] * ud));
        float z = fmaf(Cm[8], d, fmaf(Cm[7], vd, Cm[6] * ud));

        bool inb = (x > 1.0f) && (x < 41.0f) &&
                   (y > -20.0f) && (y < 20.0f) &&
                   (z > -10.0f) && (z < 10.0f);
        float fxv = floorf((x - 1.0f) * 4.0f);
        float fyv = floorf((y + 20.0f) * 4.0f);
        float fzv = floorf((z + 10.0f) / 20.0f);
        int xi = (int)fxv, yi = (int)fyv, zi = (int)fzv;
        bool ing = (xi >= 0) && (xi < NXX) && (yi >= 0) && (yi < NYY) &&
                   (zi >= 0) && (zi < 1);

        pix2seg_g[pix] = (inb && ing) ? ((b * NXX + xi) * NYY + yi) : -1;
    }
    __syncthreads();
    __threadfence();
    cudaTriggerProgrammaticLaunchCompletion();
}

// One warp per pixel. Preload (pix2seg + feats) pre-sync, then vectorized
// red.global.add.v4.f32 post-sync: chunks lane, lane+32, lane+64, lane+96(<118).
__global__ void __launch_bounds__(256)
scatter_kernel(const float* __restrict__ feats,   // [B, C, FH, FW]
               float* __restrict__ out)           // [B*NX*NY, C]
{
    int warp = (blockIdx.x * 256 + threadIdx.x) >> 5;
    int lane = threadIdx.x & 31;
    bool active = (warp < BB * NPIX);

    int seg = -1;
    if (active) seg = pix2seg_g[warp];

    int b  = warp / NPIX;
    int hw = warp - b * NPIX;
    const float* fp = feats + (size_t)b * CC * NPIX + hw;

    // preload up to 4 chunks x 4 channels = 16 floats
    float v[4][4];
    bool has4 = (lane < (NCHUNK - 96));   // lane < 22
    if (seg >= 0) {
        #pragma unroll
        for (int r = 0; r < 3; r++) {
            int c = (r * 32 + lane) * 4;
            #pragma unroll
            for (int k = 0; k < 4; k++)
                v[r][k] = __ldg(&fp[(size_t)(c + k) * NPIX]);
        }
        if (has4) {
            int c = (96 + lane) * 4;
            #pragma unroll
            for (int k = 0; k < 4; k++)
                v[3][k] = __ldg(&fp[(size_t)(c + k) * NPIX]);
        }
    }

    // wait for the fused kernel (zero-fill) to fully complete
    cudaGridDependencySynchronize();

    if (seg < 0) return;
    float* op = out + (size_t)seg * CC;
    #pragma unroll
    for (int r = 0; r < 3; r++) {
        int c = (r * 32 + lane) * 4;
        red_add_v4(&op[c], v[r][0], v[r][1], v[r][2], v[r][3]);
    }
    if (has4) {
        int c = (96 + lane) * 4;
        red_add_v4(&op[c], v[3][0], v[3][1], v[3][2], v[3][3]);
    }
}

extern "C" void kernel_launch(void* const* d_in, const int* in_sizes, int n_in,
                              void* d_out, int out_size) {
    const float* depth = (const float*)d_in[0];
    const float* feats = (const float*)d_in[1];
    const float* intr  = (const float*)d_in[2];
    const float* rot   = (const float*)d_in[3];
    float* out = (float*)d_out;

    fused_kernel<<<ARG_BLOCKS + ZERO_BLOCKS, 256>>>(depth, intr, rot, out,
                                                    (long long)out_size);

    int warps_total = BB * NPIX;                 // 44800
    int blocks = (warps_total * 32 + 255) / 256; // 5600

    cudaLaunchConfig_t cfg = {};
    cfg.gridDim  = dim3(blocks, 1, 1);
    cfg.blockDim = dim3(256, 1, 1);
    cfg.dynamicSmemBytes = 0;
    cfg.stream = 0;
    cudaLaunchAttribute attrs[1];
    attrs[0].id = cudaLaunchAttributeProgrammaticStreamSerialization;
    attrs[0].val.programmaticStreamSerializationAllowed = 1;
    cfg.attrs = attrs;
    cfg.numAttrs = 1;
    cudaLaunchKernelEx(&cfg, scatter_kernel, feats, out);
}